// round 1
// baseline (speedup 1.0000x reference)
#include <cuda_runtime.h>
#include <cuda_bf16.h>

// ALiBi bias materialization:
//   out[z, i, j] = -slopes[z % 16] * |i - j|
//   z in [0, 64)  (batch_size=4 * num_heads=16, tiled so h = z % 16)
//   i, j in [0, 2048)
// Output: 64 * 2048 * 2048 fp32 = 1 GiB  -> pure HBM-write-bound kernel.

#define S        2048
#define NUM_H    16
#define BATCH    4
#define Z_TOTAL  (BATCH * NUM_H)          // 64
#define HALF_ROW 1024                     // floats per block
#define THREADS  256                      // 256 threads * float4 = 1024 floats

__global__ __launch_bounds__(THREADS)
void alibi_kernel(const float* __restrict__ slopes, float* __restrict__ out) {
    // Block layout: 2 blocks per row, rows = Z_TOTAL * S = 131072.
    // blockIdx.x = row * 2 + half
    const unsigned bx   = blockIdx.x;
    const unsigned row  = bx >> 1;            // global row index in [0, 131072)
    const unsigned half = bx & 1u;
    const unsigned i    = row & (S - 1);      // i in [0, 2048)
    const unsigned h    = (row >> 11) & (NUM_H - 1);  // z % 16

    // Block-uniform slope (L1-cached broadcast; 16 floats total input).
    const float neg_slope = -__ldg(&slopes[h]);
    const float fi = (float)i;

    const unsigned j0 = half * HALF_ROW + threadIdx.x * 4u;
    const float fj = (float)j0;

    float4 v;
    v.x = neg_slope * fabsf(fi - fj);
    v.y = neg_slope * fabsf(fi - (fj + 1.0f));
    v.z = neg_slope * fabsf(fi - (fj + 2.0f));
    v.w = neg_slope * fabsf(fi - (fj + 3.0f));

    // Coalesced 16B store; row base = row * 2048.
    float4* dst = reinterpret_cast<float4*>(out + (size_t)row * S + j0);
    *dst = v;
}

extern "C" void kernel_launch(void* const* d_in, const int* in_sizes, int n_in,
                              void* d_out, int out_size) {
    const float* slopes = (const float*)d_in[0];
    float* out = (float*)d_out;

    // rows = 64 * 2048 = 131072, 2 blocks per row
    const unsigned grid = Z_TOTAL * S * 2;
    alibi_kernel<<<grid, THREADS>>>(slopes, out);
}